// round 16
// baseline (speedup 1.0000x reference)
#include <cuda_runtime.h>
#include <cuda_bf16.h>
#include <cuda_fp16.h>
#include <cstdint>

#define NN 100000
#define NE 1600000
#define NTILES 782
#define NSM 148

// ---------------- scratch (__device__ globals; no allocation) --------------
__device__ int    g_w64;
__device__ int    g_deg[NN];
__device__ int    g_cursor[NN];
__device__ int    g_rowptr[NN + 1];
__device__ int    g_bsum[128];
__device__ int    g_csr[NE];
__device__ float  g_inv[NN];
// fp16 gather planes (flat): [node][128] half
__device__ uint4  g_xh[(size_t)NN * 16];
__device__ uint4  g_hh[3][(size_t)NN * 16];
// blocked, PRE-SWIZZLED A images: [buf][tile][kc(4)][plane(4)][8KB]
// (mean planes 0/1 now unused; x planes 2/3 live at +16KB of each kc block)
__device__ uint4  g_ablk[4][(size_t)NTILES * 8192];
// blocked pre-swizzled weights: [l][4 planes x 32KB]
__device__ uint4  g_wblk[3 * 8192];
// blocked pre-swizzled fc weights: 12 planes x 8KB
__device__ uint4  g_fwblk[6144];

// ---------------- helpers ---------------------------------------------------
__device__ __forceinline__ void bsplit(float f, unsigned short& h, unsigned short& l) {
    __nv_bfloat16 bh = __float2bfloat16(f);
    float fh = __bfloat162float(bh);
    __nv_bfloat16 bl = __float2bfloat16(f - fh);
    h = __bfloat16_as_ushort(bh);
    l = __bfloat16_as_ushort(bl);
}
__device__ __forceinline__ uint32_t pack_h2(float a, float b) {
    __half2 p = __floats2half2_rn(a, b);
    return *reinterpret_cast<uint32_t*>(&p);
}
__device__ __forceinline__ float2 unpack_h2(uint32_t u) {
    return __half22float2(*reinterpret_cast<const __half2*>(&u));
}
__device__ __forceinline__ uint32_t smem_u32(const void* p) {
    return (uint32_t)__cvta_generic_to_shared(p);
}
__device__ __forceinline__ void ldm4(uint32_t* r, uint32_t addr) {
    asm volatile("ldmatrix.sync.aligned.m8n8.x4.shared.b16 {%0,%1,%2,%3}, [%4];"
        : "=r"(r[0]), "=r"(r[1]), "=r"(r[2]), "=r"(r[3]) : "r"(addr));
}
__device__ __forceinline__ void mma16816(float* d, const uint32_t* a, const uint32_t* b) {
    asm volatile("mma.sync.aligned.m16n8k16.row.col.f32.bf16.bf16.f32 "
        "{%0,%1,%2,%3}, {%4,%5,%6,%7}, {%8,%9}, {%0,%1,%2,%3};"
        : "+f"(d[0]), "+f"(d[1]), "+f"(d[2]), "+f"(d[3])
        : "r"(a[0]), "r"(a[1]), "r"(a[2]), "r"(a[3]), "r"(b[0]), "r"(b[1]));
}
// ---- bulk async copy + mbarrier (sm_90 baseline PTX) ----
__device__ __forceinline__ void mbar_init(uint32_t a, uint32_t c) {
    asm volatile("mbarrier.init.shared.b64 [%0], %1;" :: "r"(a), "r"(c) : "memory");
}
__device__ __forceinline__ void mbar_expect(uint32_t a, uint32_t bytes) {
    asm volatile("mbarrier.arrive.expect_tx.shared.b64 _, [%0], %1;" :: "r"(a), "r"(bytes) : "memory");
}
__device__ __forceinline__ void mbar_wait(uint32_t a, uint32_t ph) {
    asm volatile(
        "{\n\t.reg .pred P;\n\t"
        "WL%=:\n\t"
        "mbarrier.try_wait.parity.shared.b64 P, [%0], %1;\n\t"
        "@P bra WD%=;\n\t"
        "bra WL%=;\n\t"
        "WD%=:\n\t}"
        :: "r"(a), "r"(ph) : "memory");
}
__device__ __forceinline__ void bulk_g2s(uint32_t dst, const void* src, uint32_t bytes, uint32_t mbar) {
    asm volatile(
        "cp.async.bulk.shared::cluster.global.mbarrier::complete_tx::bytes [%0], [%1], %2, [%3];"
        :: "r"(dst), "l"(src), "r"(bytes), "r"(mbar) : "memory");
}
// swizzled byte offsets (identical to smem consumer addressing)
__device__ __forceinline__ uint32_t b_off(int n, int ch) {
    return (uint32_t)((n * 16 + (ch ^ (n & 7))) << 4);
}
__device__ __forceinline__ uint32_t a_off(int r, int c) {
    return (uint32_t)(((r >> 1) * 8 + ((((r & 1) << 2) + c) ^ ((r >> 1) & 7))) << 4);
}
__device__ __forceinline__ uint32_t sw_off(int row, int chunk) {
    return (uint32_t)(((row << 3) + (chunk ^ (row & 7))) << 4);
}

// ---------------- fused detect + zero --------------------------------------
__global__ void k_init(const long long* __restrict__ ei) {
    int i = blockIdx.x * blockDim.x + threadIdx.x;
    if (i < NN) { g_deg[i] = 0; g_cursor[i] = 0; }
    if (blockIdx.x == 0 && threadIdx.x < 256) {
        __shared__ int bad;
        if (threadIdx.x == 0) bad = 0;
        __syncthreads();
        long long v = ei[threadIdx.x];
        long long u = ei[threadIdx.x + 256];
        if (v < 0 || v >= NN || u < 0 || u >= NN) bad = 1;
        __syncthreads();
        if (threadIdx.x == 0) g_w64 = bad ? 0 : 1;
    }
}

// ---------------- CSR build (2 edges per thread) ----------------------------
__global__ void k_count(const void* __restrict__ ei) {
    int e2 = blockIdx.x * blockDim.x + threadIdx.x;
    if (e2 >= NE / 2) return;
    int d0, d1;
    if (g_w64) {
        longlong2 v = __ldg(&((const longlong2*)((const long long*)ei + NE))[e2]);
        d0 = (int)v.x; d1 = (int)v.y;
    } else {
        int2 v = __ldg(&((const int2*)((const int*)ei + NE))[e2]);
        d0 = v.x; d1 = v.y;
    }
    if ((unsigned)d0 < (unsigned)NN) atomicAdd(&g_deg[d0], 1);
    if ((unsigned)d1 < (unsigned)NN) atomicAdd(&g_deg[d1], 1);
}
__global__ void k_scan1() {
    __shared__ int ws[32];
    int b = blockIdx.x, tid = threadIdx.x, lane = tid & 31, wp = tid >> 5;
    int i = b * 1024 + tid;
    int v = (i < NN) ? g_deg[i] : 0;
    int s = v;
    #pragma unroll
    for (int o = 1; o < 32; o <<= 1) { int t = __shfl_up_sync(0xffffffff, s, o); if (lane >= o) s += t; }
    if (lane == 31) ws[wp] = s;
    __syncthreads();
    if (wp == 0) {
        int t = ws[lane];
        #pragma unroll
        for (int o = 1; o < 32; o <<= 1) { int u = __shfl_up_sync(0xffffffff, t, o); if (lane >= o) t += u; }
        ws[lane] = t;
    }
    __syncthreads();
    int excl = s - v + (wp ? ws[wp - 1] : 0);
    if (i < NN) {
        g_rowptr[i] = excl;
        g_inv[i] = 1.0f / (float)(v > 1 ? v : 1);
    }
    if (tid == 1023) g_bsum[b] = excl + v;
}
__global__ void k_scan23() {
    __shared__ int s_off, s_tot;
    const int nb = (NN + 1023) >> 10;  // 98
    int b = blockIdx.x, tid = threadIdx.x;
    if (tid < 32) {
        int lane = tid;
        int p = 0, t = 0;
        #pragma unroll
        for (int q = 0; q < 4; ++q) {
            int i = lane + q * 32;
            int v = (i < nb) ? g_bsum[i] : 0;
            p += (i < b) ? v : 0;
            t += v;
        }
        #pragma unroll
        for (int o = 16; o > 0; o >>= 1) {
            p += __shfl_down_sync(0xffffffff, p, o);
            t += __shfl_down_sync(0xffffffff, t, o);
        }
        if (lane == 0) { s_off = p; s_tot = t; }
    }
    __syncthreads();
    int i = b * 1024 + tid;
    if (i < NN) g_rowptr[i] += s_off;
    if (b == 0 && tid == 0) g_rowptr[NN] = s_tot;
}
__global__ void k_fill(const void* __restrict__ ei) {
    int e2 = blockIdx.x * blockDim.x + threadIdx.x;
    if (e2 >= NE / 2) return;
    int d0, d1, s0, s1;
    if (g_w64) {
        longlong2 vd = __ldg(&((const longlong2*)((const long long*)ei + NE))[e2]);
        longlong2 vs = __ldg(&((const longlong2*)ei)[e2]);
        d0 = (int)vd.x; d1 = (int)vd.y; s0 = (int)vs.x; s1 = (int)vs.y;
    } else {
        int2 vd = __ldg(&((const int2*)((const int*)ei + NE))[e2]);
        int2 vs = __ldg(&((const int2*)ei)[e2]);
        d0 = vd.x; d1 = vd.y; s0 = vs.x; s1 = vs.y;
    }
    if ((unsigned)d0 < (unsigned)NN && (unsigned)s0 < (unsigned)NN) {
        int pos = g_rowptr[d0] + atomicAdd(&g_cursor[d0], 1);
        if (pos < NE) g_csr[pos] = s0;
    }
    if ((unsigned)d1 < (unsigned)NN && (unsigned)s1 < (unsigned)NN) {
        int pos = g_rowptr[d1] + atomicAdd(&g_cursor[d1], 1);
        if (pos < NE) g_csr[pos] = s1;
    }
}

// ---------------- weight conversion: pre-swizzled blocked images -----------
__global__ void k_prepw(const float* __restrict__ Wl, const float* __restrict__ Wr,
                        const float* __restrict__ fw) {
    int id = blockIdx.x * blockDim.x + threadIdx.x;
    if (id < 3 * 2 * 128 * 128) {
        int l = id >> 15, r = id & 32767;
        int mat = r >> 14, r2 = r & 16383;
        int n = r2 >> 7, k = r2 & 127;
        const float* W = mat ? Wr : Wl;
        float w = W[(size_t)l * 16384 + k * 128 + n];
        unsigned short hs, ls; bsplit(w, hs, ls);
        char* base = (char*)g_wblk + (size_t)l * 131072;
        uint32_t off = b_off(n, k >> 3) + (k & 7) * 2;
        *(unsigned short*)(base + (mat * 2 + 0) * 32768 + off) = hs;
        *(unsigned short*)(base + (mat * 2 + 1) * 32768 + off) = ls;
    } else {
        int id2 = id - 3 * 2 * 128 * 128;
        if (id2 < 384 * 64) {
            int k = id2 >> 6, n = id2 & 63;
            float w = fw[(size_t)k * 64 + n];
            unsigned short hs, ls; bsplit(w, hs, ls);
            int cc = k >> 6, kk = k & 63;
            char* base = (char*)g_fwblk;
            uint32_t off = sw_off(n, kk >> 3) + (kk & 7) * 2;
            *(unsigned short*)(base + (cc * 2 + 0) * 8192 + off) = hs;
            *(unsigned short*)(base + (cc * 2 + 1) * 8192 + off) = ls;
        }
    }
}
// split x0 into blocked x planes of g_ablk[0] + flat fp16
__global__ void k_splitx0(const float* __restrict__ x) {
    int t = blockIdx.x * blockDim.x + threadIdx.x;
    if (t >= NN * 16) return;
    int node = t >> 4, c16 = t & 15;
    const float4* src = (const float4*)(x + (size_t)node * 128 + c16 * 8);
    float4 v0 = src[0], v1 = src[1];
    float f[8] = {v0.x, v0.y, v0.z, v0.w, v1.x, v1.y, v1.z, v1.w};
    unsigned short hs[8], ls[8];
    #pragma unroll
    for (int i = 0; i < 8; ++i) bsplit(f[i], hs[i], ls[i]);
    uint4 hv, lv, pv;
    hv.x = hs[0] | ((unsigned)hs[1] << 16); hv.y = hs[2] | ((unsigned)hs[3] << 16);
    hv.z = hs[4] | ((unsigned)hs[5] << 16); hv.w = hs[6] | ((unsigned)hs[7] << 16);
    lv.x = ls[0] | ((unsigned)ls[1] << 16); lv.y = ls[2] | ((unsigned)ls[3] << 16);
    lv.z = ls[4] | ((unsigned)ls[5] << 16); lv.w = ls[6] | ((unsigned)ls[7] << 16);
    pv.x = pack_h2(f[0], f[1]); pv.y = pack_h2(f[2], f[3]);
    pv.z = pack_h2(f[4], f[5]); pv.w = pack_h2(f[6], f[7]);
    int tile = node >> 7, r = node & 127, kc = c16 >> 2, c = c16 & 3;
    char* base = (char*)g_ablk[0] + (size_t)tile * 131072 + kc * 32768;
    *(uint4*)(base + 2 * 8192 + a_off(r, c)) = hv;
    *(uint4*)(base + 3 * 8192 + a_off(r, c)) = lv;
    g_xh[(size_t)node * 16 + c16] = pv;
}

// ---------------- FUSED persistent layer kernel: agg + GEMM -----------------
// smem: B 128KB @0; MEAN [kc(4)][hi 8KB][lo 8KB] = 64KB @131072;
//       X ring 2 x 16KB @196608; mbarriers @229376.
#define SMEM_L (131072 + 65536 + 32768 + 64)
__global__ void __launch_bounds__(512, 1) k_gemm_layer(const float* __restrict__ bias,
                                                       int layer, int tile_limit) {
    extern __shared__ char smem[];
    uint32_t sb = smem_u32(smem);
    const uint32_t MEAN = sb + 131072;
    const uint32_t XR   = sb + 196608;
    const uint32_t mb   = sb + 229376;
    const int tid = threadIdx.x;
    const int wid = tid >> 5, lane = tid & 31;
    const int warp_m = wid & 3, warp_n = wid >> 2;   // 4 x 4
    const char* asrc = (const char*)g_ablk[layer];
    const uint2* xh = (layer == 0) ? (const uint2*)g_xh : (const uint2*)g_hh[layer - 1];

    if (tid == 0) {
        mbar_init(mb + 0, 1); mbar_init(mb + 8, 1); mbar_init(mb + 24, 1);
    }
    __syncthreads();
    if (tid == 0) {
        mbar_expect(mb + 24, 131072);
        bulk_g2s(sb, (const char*)g_wblk + (size_t)layer * 131072, 131072, mb + 24);
        // x planes (kc0) of first tile -> slot 0  (16KB = planes 2,3 contiguous)
        mbar_expect(mb + 0, 16384);
        bulk_g2s(XR, asrc + (size_t)blockIdx.x * 131072 + 16384, 16384, mb + 0);
    }

    const int chA[6] = {0, 1, 0, 2, 3, 2};
    const int chB[6] = {0, 0, 1, 2, 2, 3};
    uint32_t* op = (uint32_t*)g_hh[layer];
    char* nblk = (char*)g_ablk[layer + 1];

    int sl = 0;
    int ph[2] = {0, 0};
    bool first = true;

    for (int tile = blockIdx.x; tile < tile_limit; tile += NSM) {
        int m0 = tile * 128;

        // ===== phase A: gather mean for this tile into smem MEAN planes =====
        __syncthreads();   // all warps done reading MEAN of previous tile
        #pragma unroll 1
        for (int q = 0; q < 8; ++q) {
            int node = m0 + wid * 8 + q;
            if (node >= NN) break;
            int s = g_rowptr[node], e = g_rowptr[node + 1];
            float a0 = 0.f, a1 = 0.f, a2 = 0.f, a3 = 0.f;
            float b0 = 0.f, b1 = 0.f, b2 = 0.f, b3 = 0.f;
            int p = s;
            for (; p + 7 < e; p += 8) {
                int j0 = __ldg(&g_csr[p]),     j1 = __ldg(&g_csr[p + 1]);
                int j2 = __ldg(&g_csr[p + 2]), j3 = __ldg(&g_csr[p + 3]);
                int j4 = __ldg(&g_csr[p + 4]), j5 = __ldg(&g_csr[p + 5]);
                int j6 = __ldg(&g_csr[p + 6]), j7 = __ldg(&g_csr[p + 7]);
                uint2 u0 = __ldg(&xh[(size_t)j0 * 32 + lane]);
                uint2 u1 = __ldg(&xh[(size_t)j1 * 32 + lane]);
                uint2 u2 = __ldg(&xh[(size_t)j2 * 32 + lane]);
                uint2 u3 = __ldg(&xh[(size_t)j3 * 32 + lane]);
                uint2 u4 = __ldg(&xh[(size_t)j4 * 32 + lane]);
                uint2 u5 = __ldg(&xh[(size_t)j5 * 32 + lane]);
                uint2 u6 = __ldg(&xh[(size_t)j6 * 32 + lane]);
                uint2 u7 = __ldg(&xh[(size_t)j7 * 32 + lane]);
                float2 t;
                t = unpack_h2(u0.x); a0 += t.x; a1 += t.y;
                t = unpack_h2(u0.y); a2 += t.x; a3 += t.y;
                t = unpack_h2(u1.x); b0 += t.x; b1 += t.y;
                t = unpack_h2(u1.y); b2 += t.x; b3 += t.y;
                t = unpack_h2(u2.x); a0 += t.x; a1 += t.y;
                t = unpack_h2(u2.y); a2 += t.x; a3 += t.y;
                t = unpack_h2(u3.x); b0 += t.x; b1 += t.y;
                t = unpack_h2(u3.y); b2 += t.x; b3 += t.y;
                t = unpack_h2(u4.x); a0 += t.x; a1 += t.y;
                t = unpack_h2(u4.y); a2 += t.x; a3 += t.y;
                t = unpack_h2(u5.x); b0 += t.x; b1 += t.y;
                t = unpack_h2(u5.y); b2 += t.x; b3 += t.y;
                t = unpack_h2(u6.x); a0 += t.x; a1 += t.y;
                t = unpack_h2(u6.y); a2 += t.x; a3 += t.y;
                t = unpack_h2(u7.x); b0 += t.x; b1 += t.y;
                t = unpack_h2(u7.y); b2 += t.x; b3 += t.y;
            }
            for (; p + 1 < e; p += 2) {
                int j0 = __ldg(&g_csr[p]), j1 = __ldg(&g_csr[p + 1]);
                uint2 u0 = __ldg(&xh[(size_t)j0 * 32 + lane]);
                uint2 u1 = __ldg(&xh[(size_t)j1 * 32 + lane]);
                float2 t;
                t = unpack_h2(u0.x); a0 += t.x; a1 += t.y;
                t = unpack_h2(u0.y); a2 += t.x; a3 += t.y;
                t = unpack_h2(u1.x); b0 += t.x; b1 += t.y;
                t = unpack_h2(u1.y); b2 += t.x; b3 += t.y;
            }
            if (p < e) {
                int j = __ldg(&g_csr[p]);
                uint2 u = __ldg(&xh[(size_t)j * 32 + lane]);
                float2 t;
                t = unpack_h2(u.x); a0 += t.x; a1 += t.y;
                t = unpack_h2(u.y); a2 += t.x; a3 += t.y;
            }
            a0 += b0; a1 += b1; a2 += b2; a3 += b3;
            float inv = g_inv[node];
            a0 *= inv; a1 *= inv; a2 *= inv; a3 *= inv;
            unsigned short h0, l0, h1, l1, h2, l2, h3, l3;
            bsplit(a0, h0, l0); bsplit(a1, h1, l1); bsplit(a2, h2, l2); bsplit(a3, h3, l3);
            int r = node - m0;
            int c16 = lane >> 1, kc = c16 >> 2, c = c16 & 3, sub = (lane & 1) * 8;
            char* mbase = smem + 131072 + kc * 16384;
            *(uint2*)(mbase + a_off(r, c) + sub) =
                make_uint2((unsigned)h0 | ((unsigned)h1 << 16), (unsigned)h2 | ((unsigned)h3 << 16));
            *(uint2*)(mbase + 8192 + a_off(r, c) + sub) =
                make_uint2((unsigned)l0 | ((unsigned)l1 << 16), (unsigned)l2 | ((unsigned)l3 << 16));
        }
        __syncthreads();   // MEAN visible to all warps
        if (first) { mbar_wait(mb + 24, 0); first = false; }

        // ===== phase B: MMA over 4 k-chunks =====
        float acc[2][4][4];
        #pragma unroll
        for (int mt = 0; mt < 2; ++mt)
            #pragma unroll
            for (int nt = 0; nt < 4; ++nt)
                { acc[mt][nt][0]=0.f; acc[mt][nt][1]=0.f; acc[mt][nt][2]=0.f; acc[mt][nt][3]=0.f; }

        #pragma unroll
        for (int kc = 0; kc < 4; ++kc) {
            mbar_wait(mb + sl * 8, ph[sl]); ph[sl] ^= 1;
            __syncthreads();   // x slot ready; all threads past previous chunk's mma
            if (tid == 0) {
                int nsl = sl ^ 1;
                if (kc < 3) {
                    mbar_expect(mb + nsl * 8, 16384);
                    bulk_g2s(XR + nsl * 16384,
                             asrc + (size_t)tile * 131072 + (kc + 1) * 32768 + 16384,
                             16384, mb + nsl * 8);
                } else if (tile + NSM < tile_limit) {
                    mbar_expect(mb + nsl * 8, 16384);
                    bulk_g2s(XR + nsl * 16384,
                             asrc + (size_t)(tile + NSM) * 131072 + 16384,
                             16384, mb + nsl * 8);
                }
            }
            uint32_t meanb = MEAN + kc * 16384;
            uint32_t xb = XR + sl * 16384;
            uint32_t baseA_arr[4] = {meanb, meanb + 8192, xb, xb + 8192};
            #pragma unroll
            for (int ch = 0; ch < 6; ++ch) {
                uint32_t baseA = baseA_arr[chA[ch]];
                uint32_t baseB = sb + chB[ch] * 32768;
                #pragma unroll
                for (int ks = 0; ks < 2; ++ks) {
                    int cs  = ks * 2 + (lane >> 4);
                    int bch = kc * 4 + ks * 2 + (lane >> 4);
                    uint32_t a[2][4];
                    #pragma unroll
                    for (int mt = 0; mt < 2; ++mt) {
                        int row = warp_m * 32 + mt * 16 + (lane & 15);
                        ldm4(a[mt], baseA + a_off(row, cs));
                    }
                    uint32_t b[4][2];
                    #pragma unroll
                    for (int np = 0; np < 2; ++np) {
                        int row = warp_n * 32 + np * 16 + (lane & 7) + (((lane >> 3) & 1) << 3);
                        uint32_t t[4];
                        ldm4(t, baseB + b_off(row, bch));
                        b[np * 2][0] = t[0];  b[np * 2][1] = t[2];
                        b[np * 2 + 1][0] = t[1];  b[np * 2 + 1][1] = t[3];
                    }
                    #pragma unroll
                    for (int mt = 0; mt < 2; ++mt)
                        #pragma unroll
                        for (int nt = 0; nt < 4; ++nt)
                            mma16816(acc[mt][nt], a[mt], b[nt]);
                }
            }
            sl ^= 1;
        }

        // ===== epilogue: bias+relu -> fp16 flat + blocked x planes =====
        char* tbase = nblk + (size_t)tile * 131072;
        #pragma unroll
        for (int mt = 0; mt < 2; ++mt) {
            int row0 = m0 + warp_m * 32 + mt * 16 + (lane >> 2);
            int r0 = row0 - m0;
            #pragma unroll
            for (int nt = 0; nt < 4; ++nt) {
                int col = warp_n * 32 + nt * 8 + (lane & 3) * 2;
                int c16 = col >> 3, kc2 = c16 >> 2, c2 = c16 & 3, sub = (col & 7) * 2;
                float b0 = __ldg(&bias[col]), b1 = __ldg(&bias[col + 1]);
                #pragma unroll
                for (int h = 0; h < 2; ++h) {
                    int row = row0 + h * 8;
                    if (row < NN) {
                        float f0 = fmaxf(acc[mt][nt][h * 2 + 0] + b0, 0.f);
                        float f1 = fmaxf(acc[mt][nt][h * 2 + 1] + b1, 0.f);
                        unsigned short h0, l0, h1, l1;
                        bsplit(f0, h0, l0); bsplit(f1, h1, l1);
                        uint32_t ao = a_off(r0 + h * 8, c2) + sub;
                        char* kb = tbase + kc2 * 32768;
                        *(uint32_t*)(kb + 2 * 8192 + ao) = (unsigned)h0 | ((unsigned)h1 << 16);
                        *(uint32_t*)(kb + 3 * 8192 + ao) = (unsigned)l0 | ((unsigned)l1 << 16);
                        op[(size_t)row * 64 + (col >> 1)] = pack_h2(f0, f1);
                    }
                }
            }
        }
    }
}

// ---------------- persistent final JK GEMM: bulk-copy pipelined -------------
#define SMEM_F (98304 + 3 * 32768 + 64)
__global__ void __launch_bounds__(512, 1) k_gemm_final(const float* __restrict__ fb,
                                                       float* __restrict__ out,
                                                       int tile_limit) {
    extern __shared__ char smem[];
    uint32_t sb = smem_u32(smem);
    const uint32_t mb = sb + 196608;
    const int tid = threadIdx.x;
    const int wid = tid >> 5, lane = tid & 31;
    const int warp_m = wid & 7, warp_n = wid >> 3;   // 8 x 2

    if (tid == 0) {
        mbar_init(mb + 0, 1); mbar_init(mb + 8, 1);
        mbar_init(mb + 16, 1); mbar_init(mb + 24, 1);
    }
    __syncthreads();
    auto issueA = [&](int tile, int cc, int slot) {
        int l = cc >> 1, kh = cc & 1;
        const char* src = (const char*)g_ablk[1 + l] + (size_t)tile * 131072
                        + (kh * 2) * 32768 + 16384;
        mbar_expect(mb + slot * 8, 32768);
        bulk_g2s(sb + 98304 + slot * 32768, src, 16384, mb + slot * 8);
        bulk_g2s(sb + 98304 + slot * 32768 + 16384, src + 32768, 16384, mb + slot * 8);
    };
    if (tid == 0) {
        mbar_expect(mb + 24, 98304);
        bulk_g2s(sb, (const char*)g_fwblk, 98304, mb + 24);
        issueA(blockIdx.x, 0, 0);
    }
    mbar_wait(mb + 24, 0);

    const int fA[3] = {0, 0, 1}, fB[3] = {0, 1, 0};
    int ph[3] = {0, 0, 0};

    for (int tile = blockIdx.x; tile < tile_limit; tile += NSM) {
        float acc[4][4];
        #pragma unroll
        for (int nt = 0; nt < 4; ++nt)
            { acc[nt][0]=0.f; acc[nt][1]=0.f; acc[nt][2]=0.f; acc[nt][3]=0.f; }

        #pragma unroll
        for (int cc = 0; cc < 6; ++cc) {
            int slot = cc % 3, nslot = (cc + 1) % 3;
            if (tid == 0) {
                if (cc < 5) issueA(tile, cc + 1, nslot);
                else if (tile + NSM < tile_limit) issueA(tile + NSM, 0, nslot);
            }
            mbar_wait(mb + slot * 8, ph[slot]); ph[slot] ^= 1;
            __syncthreads();

            uint32_t stb = sb + 98304 + slot * 32768;
            #pragma unroll
            for (int ch = 0; ch < 3; ++ch) {
                uint32_t baseB = sb + (cc * 2 + fB[ch]) * 8192;
                #pragma unroll
                for (int ks = 0; ks < 4; ++ks) {
                    int ch16 = ks * 2 + (lane >> 4);
                    uint32_t a[4];
                    {
                        int row = warp_m * 16 + (lane & 15);
                        uint32_t baseA = stb + (ch16 >> 2) * 16384 + fA[ch] * 8192;
                        ldm4(a, baseA + a_off(row, ch16 & 3));
                    }
                    uint32_t b[4][2];
                    #pragma unroll
                    for (int np = 0; np < 2; ++np) {
                        int row = warp_n * 32 + np * 16 + (lane & 7) + (((lane >> 3) & 1) << 3);
                        uint32_t t[4];
                        ldm4(t, baseB + sw_off(row, ch16));
                        b[np * 2][0] = t[0];  b[np * 2][1] = t[2];
                        b[np * 2 + 1][0] = t[1];  b[np * 2 + 1][1] = t[3];
                    }
                    #pragma unroll
                    for (int nt = 0; nt < 4; ++nt)
                        mma16816(acc[nt], a, b[nt]);
                }
            }
        }

        int m0 = tile * 128;
        int row0 = m0 + warp_m * 16 + (lane >> 2);
        #pragma unroll
        for (int nt = 0; nt < 4; ++nt) {
            int col = warp_n * 32 + nt * 8 + (lane & 3) * 2;
            float b0 = __ldg(&fb[col]), b1 = __ldg(&fb[col + 1]);
            #pragma unroll
            for (int h = 0; h < 2; ++h) {
                int row = row0 + h * 8;
                if (row < NN) {
                    float2 o;
                    o.x = acc[nt][h * 2 + 0] + b0;
                    o.y = acc[nt][h * 2 + 1] + b1;
                    *(float2*)&out[(size_t)row * 64 + col] = o;
                }
            }
        }
    }
}

// ---------------- launch ----------------------------------------------------
extern "C" void kernel_launch(void* const* d_in, const int* in_sizes, int n_in,
                              void* d_out, int out_size) {
    const float* x  = (const float*)d_in[0];
    const void*  ei = d_in[1];
    const float* Wl = (const float*)d_in[2];
    const float* Wr = (const float*)d_in[3];
    const float* b  = (const float*)d_in[4];
    const float* fw = (const float*)d_in[5];
    const float* fb = (const float*)d_in[6];
    float* out = (float*)d_out;

    cudaFuncSetAttribute(k_gemm_layer, cudaFuncAttributeMaxDynamicSharedMemorySize, SMEM_L);
    cudaFuncSetAttribute(k_gemm_final, cudaFuncAttributeMaxDynamicSharedMemorySize, SMEM_F);

    k_init  <<<(NN + 1023) / 1024, 1024>>>((const long long*)ei);
    k_prepw <<<(3*2*128*128 + 384*64 + 255) / 256, 256>>>(Wl, Wr, fw);
    k_splitx0<<<(NN * 16 + 255) / 256, 256>>>(x);
    k_count <<<(NE / 2 + 255) / 256, 256>>>(ei);
    k_scan1 <<<(NN + 1023) / 1024, 1024>>>();
    k_scan23<<<(NN + 1023) / 1024, 1024>>>();
    k_fill  <<<(NE / 2 + 255) / 256, 256>>>(ei);

    for (int l = 0; l < 3; ++l)
        k_gemm_layer<<<NSM, 512, SMEM_L>>>(b + (size_t)l * 128, l, NTILES);
    k_gemm_final<<<NSM, 512, SMEM_F>>>(fb, out, NTILES);
}

// round 17
// speedup vs baseline: 1.3910x; 1.3910x over previous
#include <cuda_runtime.h>
#include <cuda_bf16.h>
#include <cuda_fp16.h>
#include <cstdint>

#define NN 100000
#define NE 1600000
#define NTILES 782
#define NSM 148

// ---------------- scratch (__device__ globals; no allocation) --------------
__device__ int    g_w64;
__device__ int    g_deg[NN];
__device__ int    g_cursor[NN];
__device__ int    g_rowptr[NN + 1];
__device__ int    g_bsum[128];
__device__ int    g_csr[NE];
__device__ float  g_inv[NN];
// fp16 gather planes (flat): [node][128] half
__device__ uint4  g_xh[(size_t)NN * 16];
__device__ uint4  g_hh[3][(size_t)NN * 16];
// blocked, PRE-SWIZZLED A images: [buf][tile][kc(4)][plane(4)][8KB]
__device__ uint4  g_ablk[4][(size_t)NTILES * 8192];
// blocked pre-swizzled weights: [l][4 planes x 32KB]
__device__ uint4  g_wblk[3 * 8192];
// blocked pre-swizzled fc weights: 12 planes x 8KB
__device__ uint4  g_fwblk[6144];

// ---------------- helpers ---------------------------------------------------
__device__ __forceinline__ void bsplit(float f, unsigned short& h, unsigned short& l) {
    __nv_bfloat16 bh = __float2bfloat16(f);
    float fh = __bfloat162float(bh);
    __nv_bfloat16 bl = __float2bfloat16(f - fh);
    h = __bfloat16_as_ushort(bh);
    l = __bfloat16_as_ushort(bl);
}
__device__ __forceinline__ uint32_t pack_h2(float a, float b) {
    __half2 p = __floats2half2_rn(a, b);
    return *reinterpret_cast<uint32_t*>(&p);
}
__device__ __forceinline__ float2 unpack_h2(uint32_t u) {
    return __half22float2(*reinterpret_cast<const __half2*>(&u));
}
__device__ __forceinline__ uint32_t smem_u32(const void* p) {
    return (uint32_t)__cvta_generic_to_shared(p);
}
__device__ __forceinline__ void ldm4(uint32_t* r, uint32_t addr) {
    asm volatile("ldmatrix.sync.aligned.m8n8.x4.shared.b16 {%0,%1,%2,%3}, [%4];"
        : "=r"(r[0]), "=r"(r[1]), "=r"(r[2]), "=r"(r[3]) : "r"(addr));
}
__device__ __forceinline__ void mma16816(float* d, const uint32_t* a, const uint32_t* b) {
    asm volatile("mma.sync.aligned.m16n8k16.row.col.f32.bf16.bf16.f32 "
        "{%0,%1,%2,%3}, {%4,%5,%6,%7}, {%8,%9}, {%0,%1,%2,%3};"
        : "+f"(d[0]), "+f"(d[1]), "+f"(d[2]), "+f"(d[3])
        : "r"(a[0]), "r"(a[1]), "r"(a[2]), "r"(a[3]), "r"(b[0]), "r"(b[1]));
}
// ---- bulk async copy + mbarrier (sm_90 baseline PTX) ----
__device__ __forceinline__ void mbar_init(uint32_t a, uint32_t c) {
    asm volatile("mbarrier.init.shared.b64 [%0], %1;" :: "r"(a), "r"(c) : "memory");
}
__device__ __forceinline__ void mbar_expect(uint32_t a, uint32_t bytes) {
    asm volatile("mbarrier.arrive.expect_tx.shared.b64 _, [%0], %1;" :: "r"(a), "r"(bytes) : "memory");
}
__device__ __forceinline__ void mbar_wait(uint32_t a, uint32_t ph) {
    asm volatile(
        "{\n\t.reg .pred P;\n\t"
        "WL%=:\n\t"
        "mbarrier.try_wait.parity.shared.b64 P, [%0], %1;\n\t"
        "@P bra WD%=;\n\t"
        "bra WL%=;\n\t"
        "WD%=:\n\t}"
        :: "r"(a), "r"(ph) : "memory");
}
__device__ __forceinline__ void bulk_g2s(uint32_t dst, const void* src, uint32_t bytes, uint32_t mbar) {
    asm volatile(
        "cp.async.bulk.shared::cluster.global.mbarrier::complete_tx::bytes [%0], [%1], %2, [%3];"
        :: "r"(dst), "l"(src), "r"(bytes), "r"(mbar) : "memory");
}
__device__ __forceinline__ int m3(int v) { if (v >= 3) v -= 3; if (v >= 3) v -= 3; return v; }
// swizzled byte offsets (identical to smem consumer addressing)
__device__ __forceinline__ uint32_t b_off(int n, int ch) {
    return (uint32_t)((n * 16 + (ch ^ (n & 7))) << 4);
}
__device__ __forceinline__ uint32_t a_off(int r, int c) {
    return (uint32_t)(((r >> 1) * 8 + ((((r & 1) << 2) + c) ^ ((r >> 1) & 7))) << 4);
}
__device__ __forceinline__ uint32_t sw_off(int row, int chunk) {
    return (uint32_t)(((row << 3) + (chunk ^ (row & 7))) << 4);
}

// ---------------- fused detect + zero --------------------------------------
__global__ void k_init(const long long* __restrict__ ei) {
    int i = blockIdx.x * blockDim.x + threadIdx.x;
    if (i < NN) { g_deg[i] = 0; g_cursor[i] = 0; }
    if (blockIdx.x == 0 && threadIdx.x < 256) {
        __shared__ int bad;
        if (threadIdx.x == 0) bad = 0;
        __syncthreads();
        long long v = ei[threadIdx.x];
        long long u = ei[threadIdx.x + 256];
        if (v < 0 || v >= NN || u < 0 || u >= NN) bad = 1;
        __syncthreads();
        if (threadIdx.x == 0) g_w64 = bad ? 0 : 1;
    }
}

// ---------------- CSR build (2 edges per thread) ----------------------------
__global__ void k_count(const void* __restrict__ ei) {
    int e2 = blockIdx.x * blockDim.x + threadIdx.x;
    if (e2 >= NE / 2) return;
    int d0, d1;
    if (g_w64) {
        longlong2 v = __ldg(&((const longlong2*)((const long long*)ei + NE))[e2]);
        d0 = (int)v.x; d1 = (int)v.y;
    } else {
        int2 v = __ldg(&((const int2*)((const int*)ei + NE))[e2]);
        d0 = v.x; d1 = v.y;
    }
    if ((unsigned)d0 < (unsigned)NN) atomicAdd(&g_deg[d0], 1);
    if ((unsigned)d1 < (unsigned)NN) atomicAdd(&g_deg[d1], 1);
}
__global__ void k_scan1() {
    __shared__ int ws[32];
    int b = blockIdx.x, tid = threadIdx.x, lane = tid & 31, wp = tid >> 5;
    int i = b * 1024 + tid;
    int v = (i < NN) ? g_deg[i] : 0;
    int s = v;
    #pragma unroll
    for (int o = 1; o < 32; o <<= 1) { int t = __shfl_up_sync(0xffffffff, s, o); if (lane >= o) s += t; }
    if (lane == 31) ws[wp] = s;
    __syncthreads();
    if (wp == 0) {
        int t = ws[lane];
        #pragma unroll
        for (int o = 1; o < 32; o <<= 1) { int u = __shfl_up_sync(0xffffffff, t, o); if (lane >= o) t += u; }
        ws[lane] = t;
    }
    __syncthreads();
    int excl = s - v + (wp ? ws[wp - 1] : 0);
    if (i < NN) {
        g_rowptr[i] = excl;
        g_inv[i] = 1.0f / (float)(v > 1 ? v : 1);
    }
    if (tid == 1023) g_bsum[b] = excl + v;
}
__global__ void k_scan23() {
    __shared__ int s_off, s_tot;
    const int nb = (NN + 1023) >> 10;  // 98
    int b = blockIdx.x, tid = threadIdx.x;
    if (tid < 32) {
        int lane = tid;
        int p = 0, t = 0;
        #pragma unroll
        for (int q = 0; q < 4; ++q) {
            int i = lane + q * 32;
            int v = (i < nb) ? g_bsum[i] : 0;
            p += (i < b) ? v : 0;
            t += v;
        }
        #pragma unroll
        for (int o = 16; o > 0; o >>= 1) {
            p += __shfl_down_sync(0xffffffff, p, o);
            t += __shfl_down_sync(0xffffffff, t, o);
        }
        if (lane == 0) { s_off = p; s_tot = t; }
    }
    __syncthreads();
    int i = b * 1024 + tid;
    if (i < NN) g_rowptr[i] += s_off;
    if (b == 0 && tid == 0) g_rowptr[NN] = s_tot;
}
__global__ void k_fill(const void* __restrict__ ei) {
    int e2 = blockIdx.x * blockDim.x + threadIdx.x;
    if (e2 >= NE / 2) return;
    int d0, d1, s0, s1;
    if (g_w64) {
        longlong2 vd = __ldg(&((const longlong2*)((const long long*)ei + NE))[e2]);
        longlong2 vs = __ldg(&((const longlong2*)ei)[e2]);
        d0 = (int)vd.x; d1 = (int)vd.y; s0 = (int)vs.x; s1 = (int)vs.y;
    } else {
        int2 vd = __ldg(&((const int2*)((const int*)ei + NE))[e2]);
        int2 vs = __ldg(&((const int2*)ei)[e2]);
        d0 = vd.x; d1 = vd.y; s0 = vs.x; s1 = vs.y;
    }
    if ((unsigned)d0 < (unsigned)NN && (unsigned)s0 < (unsigned)NN) {
        int pos = g_rowptr[d0] + atomicAdd(&g_cursor[d0], 1);
        if (pos < NE) g_csr[pos] = s0;
    }
    if ((unsigned)d1 < (unsigned)NN && (unsigned)s1 < (unsigned)NN) {
        int pos = g_rowptr[d1] + atomicAdd(&g_cursor[d1], 1);
        if (pos < NE) g_csr[pos] = s1;
    }
}

// ---------------- weight conversion: pre-swizzled blocked images -----------
__global__ void k_prepw(const float* __restrict__ Wl, const float* __restrict__ Wr,
                        const float* __restrict__ fw) {
    int id = blockIdx.x * blockDim.x + threadIdx.x;
    if (id < 3 * 2 * 128 * 128) {
        int l = id >> 15, r = id & 32767;
        int mat = r >> 14, r2 = r & 16383;
        int n = r2 >> 7, k = r2 & 127;
        const float* W = mat ? Wr : Wl;
        float w = W[(size_t)l * 16384 + k * 128 + n];
        unsigned short hs, ls; bsplit(w, hs, ls);
        char* base = (char*)g_wblk + (size_t)l * 131072;
        uint32_t off = b_off(n, k >> 3) + (k & 7) * 2;
        *(unsigned short*)(base + (mat * 2 + 0) * 32768 + off) = hs;
        *(unsigned short*)(base + (mat * 2 + 1) * 32768 + off) = ls;
    } else {
        int id2 = id - 3 * 2 * 128 * 128;
        if (id2 < 384 * 64) {
            int k = id2 >> 6, n = id2 & 63;
            float w = fw[(size_t)k * 64 + n];
            unsigned short hs, ls; bsplit(w, hs, ls);
            int cc = k >> 6, kk = k & 63;
            char* base = (char*)g_fwblk;
            uint32_t off = sw_off(n, kk >> 3) + (kk & 7) * 2;
            *(unsigned short*)(base + (cc * 2 + 0) * 8192 + off) = hs;
            *(unsigned short*)(base + (cc * 2 + 1) * 8192 + off) = ls;
        }
    }
}
// split x0 into blocked x planes of g_ablk[0] + flat fp16
__global__ void k_splitx0(const float* __restrict__ x) {
    int t = blockIdx.x * blockDim.x + threadIdx.x;   // over NN*16 16B-chunks
    if (t >= NN * 16) return;
    int node = t >> 4, c16 = t & 15;
    const float4* src = (const float4*)(x + (size_t)node * 128 + c16 * 8);
    float4 v0 = src[0], v1 = src[1];
    float f[8] = {v0.x, v0.y, v0.z, v0.w, v1.x, v1.y, v1.z, v1.w};
    unsigned short hs[8], ls[8];
    #pragma unroll
    for (int i = 0; i < 8; ++i) bsplit(f[i], hs[i], ls[i]);
    uint4 hv, lv, pv;
    hv.x = hs[0] | ((unsigned)hs[1] << 16); hv.y = hs[2] | ((unsigned)hs[3] << 16);
    hv.z = hs[4] | ((unsigned)hs[5] << 16); hv.w = hs[6] | ((unsigned)hs[7] << 16);
    lv.x = ls[0] | ((unsigned)ls[1] << 16); lv.y = ls[2] | ((unsigned)ls[3] << 16);
    lv.z = ls[4] | ((unsigned)ls[5] << 16); lv.w = ls[6] | ((unsigned)ls[7] << 16);
    pv.x = pack_h2(f[0], f[1]); pv.y = pack_h2(f[2], f[3]);
    pv.z = pack_h2(f[4], f[5]); pv.w = pack_h2(f[6], f[7]);
    int tile = node >> 7, r = node & 127, kc = c16 >> 2, c = c16 & 3;
    char* base = (char*)g_ablk[0] + (size_t)tile * 131072 + kc * 32768;
    *(uint4*)(base + 2 * 8192 + a_off(r, c)) = hv;
    *(uint4*)(base + 3 * 8192 + a_off(r, c)) = lv;
    g_xh[(size_t)node * 16 + c16] = pv;
}

// ---------------- mean aggregation: warp per node, MLP-4 batched -----------
__global__ void __launch_bounds__(256) k_agg(int layer) {
    int gt = blockIdx.x * blockDim.x + threadIdx.x;
    int wp = gt >> 5, lane = gt & 31;
    if (wp >= NN) return;
    int s = g_rowptr[wp], e = g_rowptr[wp + 1];
    const uint2* xh = (layer == 0) ? (const uint2*)g_xh : (const uint2*)g_hh[layer - 1];
    float a0 = 0.f, a1 = 0.f, a2 = 0.f, a3 = 0.f;
    float b0 = 0.f, b1 = 0.f, b2 = 0.f, b3 = 0.f;
    int p = s;
    for (; p + 3 < e; p += 4) {
        int j0 = __ldg(&g_csr[p]);
        int j1 = __ldg(&g_csr[p + 1]);
        int j2 = __ldg(&g_csr[p + 2]);
        int j3 = __ldg(&g_csr[p + 3]);
        uint2 u0 = __ldg(&xh[(size_t)j0 * 32 + lane]);
        uint2 u1 = __ldg(&xh[(size_t)j1 * 32 + lane]);
        uint2 u2 = __ldg(&xh[(size_t)j2 * 32 + lane]);
        uint2 u3 = __ldg(&xh[(size_t)j3 * 32 + lane]);
        float2 t;
        t = unpack_h2(u0.x); a0 += t.x; a1 += t.y;
        t = unpack_h2(u0.y); a2 += t.x; a3 += t.y;
        t = unpack_h2(u1.x); b0 += t.x; b1 += t.y;
        t = unpack_h2(u1.y); b2 += t.x; b3 += t.y;
        t = unpack_h2(u2.x); a0 += t.x; a1 += t.y;
        t = unpack_h2(u2.y); a2 += t.x; a3 += t.y;
        t = unpack_h2(u3.x); b0 += t.x; b1 += t.y;
        t = unpack_h2(u3.y); b2 += t.x; b3 += t.y;
    }
    if (p + 1 < e) {
        int j0 = __ldg(&g_csr[p]);
        int j1 = __ldg(&g_csr[p + 1]);
        uint2 u0 = __ldg(&xh[(size_t)j0 * 32 + lane]);
        uint2 u1 = __ldg(&xh[(size_t)j1 * 32 + lane]);
        float2 t;
        t = unpack_h2(u0.x); a0 += t.x; a1 += t.y;
        t = unpack_h2(u0.y); a2 += t.x; a3 += t.y;
        t = unpack_h2(u1.x); b0 += t.x; b1 += t.y;
        t = unpack_h2(u1.y); b2 += t.x; b3 += t.y;
        p += 2;
    }
    if (p < e) {
        int j = __ldg(&g_csr[p]);
        uint2 u = __ldg(&xh[(size_t)j * 32 + lane]);
        float2 t;
        t = unpack_h2(u.x); a0 += t.x; a1 += t.y;
        t = unpack_h2(u.y); a2 += t.x; a3 += t.y;
    }
    a0 += b0; a1 += b1; a2 += b2; a3 += b3;
    float inv = g_inv[wp];
    a0 *= inv; a1 *= inv; a2 *= inv; a3 *= inv;
    unsigned short h0, l0, h1, l1, h2, l2, h3, l3;
    bsplit(a0, h0, l0); bsplit(a1, h1, l1); bsplit(a2, h2, l2); bsplit(a3, h3, l3);
    // blocked mean planes (0 hi, 1 lo): lane covers cols lane*4..lane*4+3 (8B)
    int tile = wp >> 7, r = wp & 127;
    int c16 = lane >> 1, kc = c16 >> 2, c = c16 & 3, sub = (lane & 1) * 8;
    char* base = (char*)g_ablk[layer] + (size_t)tile * 131072 + kc * 32768;
    *(uint2*)(base + a_off(r, c) + sub) =
        make_uint2((unsigned)h0 | ((unsigned)h1 << 16), (unsigned)h2 | ((unsigned)h3 << 16));
    *(uint2*)(base + 8192 + a_off(r, c) + sub) =
        make_uint2((unsigned)l0 | ((unsigned)l1 << 16), (unsigned)l2 | ((unsigned)l3 << 16));
}

// ---------------- persistent layer GEMM: bulk-copy pipelined ----------------
#define SMEM_L (131072 + 3 * 32768 + 64)
__global__ void __launch_bounds__(512, 1) k_gemm_layer(const float* __restrict__ bias,
                                                       int layer, int tile_limit) {
    extern __shared__ char smem[];
    uint32_t sb = smem_u32(smem);
    const uint32_t mb = sb + 229376;
    const int tid = threadIdx.x;
    const int wid = tid >> 5, lane = tid & 31;
    const int warp_m = wid & 3, warp_n = wid >> 2;   // 4 x 4
    const char* asrc = (const char*)g_ablk[layer];

    if (tid == 0) {
        mbar_init(mb + 0, 1); mbar_init(mb + 8, 1);
        mbar_init(mb + 16, 1); mbar_init(mb + 24, 1);
    }
    __syncthreads();
    if (tid == 0) {
        mbar_expect(mb + 24, 131072);
        bulk_g2s(sb, (const char*)g_wblk + (size_t)layer * 131072, 131072, mb + 24);
        mbar_expect(mb + 0, 32768);
        bulk_g2s(sb + 131072, asrc + (size_t)blockIdx.x * 131072, 32768, mb + 0);
    }
    mbar_wait(mb + 24, 0);   // B resident

    const int chA[6] = {0, 1, 0, 2, 3, 2};
    const int chB[6] = {0, 0, 1, 2, 2, 3};
    uint32_t* op = (uint32_t*)g_hh[layer];
    char* nblk = (char*)g_ablk[layer + 1];

    int ph[3] = {0, 0, 0};
    int base = 0;

    for (int tile = blockIdx.x; tile < tile_limit; tile += NSM) {
        float acc[2][4][4];
        #pragma unroll
        for (int mt = 0; mt < 2; ++mt)
            #pragma unroll
            for (int nt = 0; nt < 4; ++nt)
                { acc[mt][nt][0]=0.f; acc[mt][nt][1]=0.f; acc[mt][nt][2]=0.f; acc[mt][nt][3]=0.f; }

        #pragma unroll
        for (int kc = 0; kc < 4; ++kc) {
            int slot = m3(base + kc), nslot = m3(base + kc + 1);
            if (tid == 0) {
                if (kc < 3) {
                    mbar_expect(mb + nslot * 8, 32768);
                    bulk_g2s(sb + 131072 + nslot * 32768,
                             asrc + (size_t)tile * 131072 + (kc + 1) * 32768, 32768, mb + nslot * 8);
                } else if (tile + NSM < tile_limit) {
                    mbar_expect(mb + nslot * 8, 32768);
                    bulk_g2s(sb + 131072 + nslot * 32768,
                             asrc + (size_t)(tile + NSM) * 131072, 32768, mb + nslot * 8);
                }
            }
            mbar_wait(mb + slot * 8, ph[slot]); ph[slot] ^= 1;
            __syncthreads();

            uint32_t stb = sb + 131072 + slot * 32768;
            #pragma unroll
            for (int ch = 0; ch < 6; ++ch) {
                uint32_t baseA = stb + chA[ch] * 8192;
                uint32_t baseB = sb + chB[ch] * 32768;
                #pragma unroll
                for (int ks = 0; ks < 2; ++ks) {
                    int cs  = ks * 2 + (lane >> 4);
                    int bch = kc * 4 + ks * 2 + (lane >> 4);
                    uint32_t a[2][4];
                    #pragma unroll
                    for (int mt = 0; mt < 2; ++mt) {
                        int row = warp_m * 32 + mt * 16 + (lane & 15);
                        ldm4(a[mt], baseA + a_off(row, cs));
                    }
                    uint32_t b[4][2];
                    #pragma unroll
                    for (int np = 0; np < 2; ++np) {
                        int row = warp_n * 32 + np * 16 + (lane & 7) + (((lane >> 3) & 1) << 3);
                        uint32_t t[4];
                        ldm4(t, baseB + b_off(row, bch));
                        b[np * 2][0] = t[0];  b[np * 2][1] = t[2];
                        b[np * 2 + 1][0] = t[1];  b[np * 2 + 1][1] = t[3];
                    }
                    #pragma unroll
                    for (int mt = 0; mt < 2; ++mt)
                        #pragma unroll
                        for (int nt = 0; nt < 4; ++nt)
                            mma16816(acc[mt][nt], a[mt], b[nt]);
                }
            }
        }
        base = m3(base + 1);

        // epilogue: bias+relu -> fp16 flat + blocked x planes of next buffer
        int m0 = tile * 128;
        char* tbase = nblk + (size_t)tile * 131072;
        #pragma unroll
        for (int mt = 0; mt < 2; ++mt) {
            int row0 = m0 + warp_m * 32 + mt * 16 + (lane >> 2);
            int r0 = row0 - m0;
            #pragma unroll
            for (int nt = 0; nt < 4; ++nt) {
                int col = warp_n * 32 + nt * 8 + (lane & 3) * 2;
                int c16 = col >> 3, kc2 = c16 >> 2, c2 = c16 & 3, sub = (col & 7) * 2;
                float b0 = __ldg(&bias[col]), b1 = __ldg(&bias[col + 1]);
                #pragma unroll
                for (int h = 0; h < 2; ++h) {
                    int row = row0 + h * 8;
                    if (row < NN) {
                        float f0 = fmaxf(acc[mt][nt][h * 2 + 0] + b0, 0.f);
                        float f1 = fmaxf(acc[mt][nt][h * 2 + 1] + b1, 0.f);
                        unsigned short h0, l0, h1, l1;
                        bsplit(f0, h0, l0); bsplit(f1, h1, l1);
                        uint32_t ao = a_off(r0 + h * 8, c2) + sub;
                        char* kb = tbase + kc2 * 32768;
                        *(uint32_t*)(kb + 2 * 8192 + ao) = (unsigned)h0 | ((unsigned)h1 << 16);
                        *(uint32_t*)(kb + 3 * 8192 + ao) = (unsigned)l0 | ((unsigned)l1 << 16);
                        op[(size_t)row * 64 + (col >> 1)] = pack_h2(f0, f1);
                    }
                }
            }
        }
    }
}

// ---------------- persistent final JK GEMM: bulk-copy pipelined -------------
#define SMEM_F (98304 + 3 * 32768 + 64)
__global__ void __launch_bounds__(512, 1) k_gemm_final(const float* __restrict__ fb,
                                                       float* __restrict__ out,
                                                       int tile_limit) {
    extern __shared__ char smem[];
    uint32_t sb = smem_u32(smem);
    const uint32_t mb = sb + 196608;
    const int tid = threadIdx.x;
    const int wid = tid >> 5, lane = tid & 31;
    const int warp_m = wid & 7, warp_n = wid >> 3;   // 8 x 2

    if (tid == 0) {
        mbar_init(mb + 0, 1); mbar_init(mb + 8, 1);
        mbar_init(mb + 16, 1); mbar_init(mb + 24, 1);
    }
    __syncthreads();
    auto issueA = [&](int tile, int cc, int slot) {
        int l = cc >> 1, kh = cc & 1;
        const char* src = (const char*)g_ablk[1 + l] + (size_t)tile * 131072
                        + (kh * 2) * 32768 + 16384;
        mbar_expect(mb + slot * 8, 32768);
        bulk_g2s(sb + 98304 + slot * 32768, src, 16384, mb + slot * 8);
        bulk_g2s(sb + 98304 + slot * 32768 + 16384, src + 32768, 16384, mb + slot * 8);
    };
    if (tid == 0) {
        mbar_expect(mb + 24, 98304);
        bulk_g2s(sb, (const char*)g_fwblk, 98304, mb + 24);
        issueA(blockIdx.x, 0, 0);
    }
    mbar_wait(mb + 24, 0);

    const int fA[3] = {0, 0, 1}, fB[3] = {0, 1, 0};
    int ph[3] = {0, 0, 0};

    for (int tile = blockIdx.x; tile < tile_limit; tile += NSM) {
        float acc[4][4];
        #pragma unroll
        for (int nt = 0; nt < 4; ++nt)
            { acc[nt][0]=0.f; acc[nt][1]=0.f; acc[nt][2]=0.f; acc[nt][3]=0.f; }

        #pragma unroll
        for (int cc = 0; cc < 6; ++cc) {
            int slot = cc % 3, nslot = (cc + 1) % 3;
            if (tid == 0) {
                if (cc < 5) issueA(tile, cc + 1, nslot);
                else if (tile + NSM < tile_limit) issueA(tile + NSM, 0, nslot);
            }
            mbar_wait(mb + slot * 8, ph[slot]); ph[slot] ^= 1;
            __syncthreads();

            uint32_t stb = sb + 98304 + slot * 32768;
            #pragma unroll
            for (int ch = 0; ch < 3; ++ch) {
                uint32_t baseB = sb + (cc * 2 + fB[ch]) * 8192;
                #pragma unroll
                for (int ks = 0; ks < 4; ++ks) {
                    int ch16 = ks * 2 + (lane >> 4);
                    uint32_t a[4];
                    {
                        int row = warp_m * 16 + (lane & 15);
                        uint32_t baseA = stb + (ch16 >> 2) * 16384 + fA[ch] * 8192;
                        ldm4(a, baseA + a_off(row, ch16 & 3));
                    }
                    uint32_t b[4][2];
                    #pragma unroll
                    for (int np = 0; np < 2; ++np) {
                        int row = warp_n * 32 + np * 16 + (lane & 7) + (((lane >> 3) & 1) << 3);
                        uint32_t t[4];
                        ldm4(t, baseB + sw_off(row, ch16));
                        b[np * 2][0] = t[0];  b[np * 2][1] = t[2];
                        b[np * 2 + 1][0] = t[1];  b[np * 2 + 1][1] = t[3];
                    }
                    #pragma unroll
                    for (int nt = 0; nt < 4; ++nt)
                        mma16816(acc[nt], a, b[nt]);
                }
            }
        }

        int m0 = tile * 128;
        int row0 = m0 + warp_m * 16 + (lane >> 2);
        #pragma unroll
        for (int nt = 0; nt < 4; ++nt) {
            int col = warp_n * 32 + nt * 8 + (lane & 3) * 2;
            float b0 = __ldg(&fb[col]), b1 = __ldg(&fb[col + 1]);
            #pragma unroll
            for (int h = 0; h < 2; ++h) {
                int row = row0 + h * 8;
                if (row < NN) {
                    float2 o;
                    o.x = acc[nt][h * 2 + 0] + b0;
                    o.y = acc[nt][h * 2 + 1] + b1;
                    *(float2*)&out[(size_t)row * 64 + col] = o;
                }
            }
        }
    }
}

// ---------------- launch (forked-stream capture for prologue overlap) -------
extern "C" void kernel_launch(void* const* d_in, const int* in_sizes, int n_in,
                              void* d_out, int out_size) {
    const float* x  = (const float*)d_in[0];
    const void*  ei = d_in[1];
    const float* Wl = (const float*)d_in[2];
    const float* Wr = (const float*)d_in[3];
    const float* b  = (const float*)d_in[4];
    const float* fw = (const float*)d_in[5];
    const float* fb = (const float*)d_in[6];
    float* out = (float*)d_out;

    cudaFuncSetAttribute(k_gemm_layer, cudaFuncAttributeMaxDynamicSharedMemorySize, SMEM_L);
    cudaFuncSetAttribute(k_gemm_final, cudaFuncAttributeMaxDynamicSharedMemorySize, SMEM_F);

    // side stream + events (host-side objects only; a handful per process run —
    // kernel_launch is invoked a small fixed number of times, replays use the graph)
    cudaStream_t s2;
    cudaStreamCreateWithFlags(&s2, cudaStreamNonBlocking);
    cudaEvent_t evFork, evJoin;
    cudaEventCreateWithFlags(&evFork, cudaEventDisableTiming);
    cudaEventCreateWithFlags(&evJoin, cudaEventDisableTiming);

    // CSR chain head on main stream (zeroes g_deg/g_cursor, sets g_w64)
    k_init<<<(NN + 1023) / 1024, 1024>>>((const long long*)ei);
    cudaEventRecord(evFork, 0);
    cudaStreamWaitEvent(s2, evFork, 0);

    // side stream: CSR chain
    k_count <<<(NE / 2 + 255) / 256, 256, 0, s2>>>(ei);
    k_scan1 <<<(NN + 1023) / 1024, 1024, 0, s2>>>();
    k_scan23<<<(NN + 1023) / 1024, 1024, 0, s2>>>();
    k_fill  <<<(NE / 2 + 255) / 256, 256, 0, s2>>>(ei);
    cudaEventRecord(evJoin, s2);

    // main stream (concurrent): weight + input prep
    k_prepw <<<(3*2*128*128 + 384*64 + 255) / 256, 256>>>(Wl, Wr, fw);
    k_splitx0<<<(NN * 16 + 255) / 256, 256>>>(x);

    // join: layer loop needs CSR + prep
    cudaStreamWaitEvent(0, evJoin, 0);

    for (int l = 0; l < 3; ++l) {
        k_agg<<<(NN * 32 + 255) / 256, 256>>>(l);
        k_gemm_layer<<<NSM, 512, SMEM_L>>>(b + (size_t)l * 128, l, NTILES);
    }
    k_gemm_final<<<NSM, 512, SMEM_F>>>(fb, out, NTILES);
}